// round 13
// baseline (speedup 1.0000x reference)
#include <cuda_runtime.h>
#include <cstdint>

#define KMAX 21
#define GNUM 20
#define WT   16                      // pixels per warp-tile (2 MMA chunks)
#define NW   8                       // warps per block
#define BT   (NW * 32)               // 256
#define GRID 444                     // 3 blocks/SM
#define NSTAGE 3
#define EPSF 1e-6f

#define SEG_SL_F (WT * KMAX)         // 336 floats
#define SEG_SL_B (SEG_SL_F * 4)      // 1344 B (84 x 16B chunks)
#define GT_ROW_W 20                  // padded plane stride (words): 80B,16B-aligned;
                                     // B-frag bank (20*gid+tig)%32 hits all 32 banks
#define GT_SL_B  (GNUM * GT_ROW_W * 4)   // 1600 B
#define SLICE_B  (SEG_SL_B + GT_SL_B)    // 2944 B
#define SC_B     (KMAX * 24 * 4)
#define SMEM_TOTAL (NW * NSTAGE * SLICE_B + SC_B + 16)   // ~72.7 KB

__device__ float g_A[KMAX * GNUM];
__device__ int   g_count;

__global__ void ms_init_kernel() {
    int t = threadIdx.x;
    if (t < KMAX * GNUM) g_A[t] = 0.0f;
    if (t == 0) g_count = 0;
}

__device__ __forceinline__ void cpasync16(uint32_t dst, const void* src) {
    asm volatile("cp.async.cg.shared.global [%0], [%1], 16;" :: "r"(dst), "l"(src));
}
__device__ __forceinline__ void cp_commit() { asm volatile("cp.async.commit_group;"); }
__device__ __forceinline__ void cp_wait2()  { asm volatile("cp.async.wait_group 2;"); }

__device__ __forceinline__ float dval(float p) {
    // log2 = positive multiple of ln -> same argmax as reference.
    return __log2f(p + EPSF) - __log2f(1.0f - p + EPSF);
}

// C[16x8] += A[16x8 tf32] x B[8x8 tf32]; fragment layouts validated in R11.
#define MMA8(c, A, B) asm volatile( \
    "mma.sync.aligned.m16n8k8.row.col.f32.tf32.tf32.f32 " \
    "{%0,%1,%2,%3}, {%4,%5,%6,%7}, {%8,%9}, {%0,%1,%2,%3};" \
    : "+f"((c)[0]), "+f"((c)[1]), "+f"((c)[2]), "+f"((c)[3]) \
    : "r"((A)[0]), "r"((A)[1]), "r"((A)[2]), "r"((A)[3]), \
      "r"((B)[0]), "r"((B)[1]))

// A[k,g] = sum_p d[p,k]*gt[g,p] as split-K GEMM; each warp is an autonomous
// 3-stage cp.async pipeline over its own pixel range (no cross-warp sharing,
// no per-tile block barriers).
__global__ __launch_bounds__(BT, 3) void ms_accum_kernel(
    const void* bufA, const void* bufB, int n, float* __restrict__ out)
{
    extern __shared__ __align__(16) char smem[];
    float* sC     = (float*)(smem + NW * NSTAGE * SLICE_B);
    int*   s_last = (int*)(smem + NW * NSTAGE * SLICE_B + SC_B);

    const int tid  = threadIdx.x;
    const int lane = tid & 31;
    const int wid  = tid >> 5;
    const int tig  = lane & 3;
    const int gid  = lane >> 2;

    // ---- buffer-identity probe (gt words are {0,1}) ----
    const unsigned wA = ((const unsigned*)bufA)[lane];
    const bool a_is_gt = (__ballot_sync(0xffffffffu, wA > 1u) == 0u);
    const float* seg = (const float*)(a_is_gt ? bufB : bufA);  // (N,21) f32
    const int*   gtp = (const int*)  (a_is_gt ? bufA : bufB);  // (21,N) {0,1}

    for (int i = tid; i < KMAX * 24; i += BT) sC[i] = 0.0f;
    __syncthreads();

    // ---- balanced warp-tile range ----
    const int gw   = blockIdx.x * NW + wid;
    const int GW   = GRID * NW;
    const int totT = (n + WT - 1) / WT;
    const int w0 = (int)(((long long)gw * totT) / GW);
    const int w1 = (int)(((long long)(gw + 1) * totT) / GW);

    char* mySl = smem + wid * NSTAGE * SLICE_B;

    auto prefetch = [&](int t) {
        if (t < w1) {
            const int base = t * WT;
            const int cnt  = min(WT, n - base);
            char* sl = mySl + (t % NSTAGE) * SLICE_B;
            const uint32_t segd = (uint32_t)__cvta_generic_to_shared(sl);
            const uint32_t gtd  = segd + SEG_SL_B;
            if (cnt == WT) {
                const float* sb = seg + (long long)base * KMAX;  // 16B-aligned
                for (int c = lane; c < SEG_SL_B / 16; c += 32)   // 84 chunks
                    cpasync16(segd + c * 16, sb + c * 4);
                for (int c = lane; c < GNUM * (WT / 4); c += 32) { // 80 chunks
                    const int g = c >> 2, ch = c & 3;
                    cpasync16(gtd + (g * GT_ROW_W + ch * 4) * 4,
                              gtp + (long long)g * n + base + ch * 4);
                }
            } else {
                // ragged tail (unused when 16|n): scalar, zero-pad (B=0 kills)
                for (int i = lane; i < SEG_SL_F; i += 32) {
                    float v = (i < cnt * KMAX)
                        ? __ldg(seg + (long long)base * KMAX + i) : 0.5f;
                    *(float*)(sl + i * 4) = v;
                }
                for (int i = lane; i < GNUM * WT; i += 32) {
                    const int g = i >> 4, p = i & 15;
                    const int v = (p < cnt)
                        ? __ldg(gtp + (long long)g * n + base + p) : 0;
                    *(int*)(sl + SEG_SL_B + (g * GT_ROW_W + p) * 4) = v;
                }
            }
        }
        cp_commit();          // unconditional: keeps group count consistent
    };

    float acc[6][4];
    #pragma unroll
    for (int i = 0; i < 6; i++)
        #pragma unroll
        for (int j = 0; j < 4; j++) acc[i][j] = 0.0f;

    prefetch(w0);
    prefetch(w0 + 1);
    prefetch(w0 + 2);

    for (int t = w0; t < w1; t++) {
        cp_wait2();
        __syncwarp();

        const char*  sl  = mySl + (t % NSTAGE) * SLICE_B;
        const float* ss  = (const float*)sl;
        const int*   gts = (const int*)(sl + SEG_SL_B);

        #pragma unroll
        for (int ch = 0; ch < WT / 8; ch++) {
            const int p0 = ch * 8 + tig, p1 = p0 + 4;

            // A frags: d computed inline, each (p,k) exactly once
            uint32_t a0[4], a1[4];
            a0[0] = __float_as_uint(dval(ss[p0 * KMAX + gid]));
            a0[1] = __float_as_uint(dval(ss[p0 * KMAX + gid + 8]));
            a0[2] = __float_as_uint(dval(ss[p1 * KMAX + gid]));
            a0[3] = __float_as_uint(dval(ss[p1 * KMAX + gid + 8]));
            const int r2 = 16 + gid;
            const int r2s = (r2 < KMAX) ? r2 : 0;
            float e0 = dval(ss[p0 * KMAX + r2s]);
            float e1 = dval(ss[p1 * KMAX + r2s]);
            if (r2 >= KMAX) { e0 = 0.0f; e1 = 0.0f; }
            a1[0] = __float_as_uint(e0);
            a1[1] = 0u;
            a1[2] = __float_as_uint(e1);
            a1[3] = 0u;

            // B frags: gi as 0.0/1.0; stride 20 words -> conflict-free
            uint32_t b[3][2];
            #pragma unroll
            for (int nt = 0; nt < 3; nt++) {
                const int nn = nt * 8 + gid;
                float f0 = 0.0f, f1 = 0.0f;
                if (nn < GNUM) {
                    f0 = (float)gts[nn * GT_ROW_W + p0];
                    f1 = (float)gts[nn * GT_ROW_W + p1];
                }
                b[nt][0] = __float_as_uint(f0);
                b[nt][1] = __float_as_uint(f1);
            }

            #pragma unroll
            for (int nt = 0; nt < 3; nt++) {
                MMA8(acc[nt],     a0, b[nt]);   // planes 0..15
                MMA8(acc[3 + nt], a1, b[nt]);   // planes 16..20
            }
        }
        __syncwarp();
        prefetch(t + NSTAGE);
    }

    // ---- C frags -> smem block reduce ----
    #pragma unroll
    for (int mt = 0; mt < 2; mt++) {
        #pragma unroll
        for (int nt = 0; nt < 3; nt++) {
            const float* c = acc[mt * 3 + nt];
            const int r0 = mt * 16 + gid, r1 = r0 + 8;
            const int c0 = nt * 8 + 2 * tig, c1 = c0 + 1;
            if (r0 < KMAX && c0 < GNUM) atomicAdd(&sC[r0 * 24 + c0], c[0]);
            if (r0 < KMAX && c1 < GNUM) atomicAdd(&sC[r0 * 24 + c1], c[1]);
            if (r1 < KMAX && c0 < GNUM) atomicAdd(&sC[r1 * 24 + c0], c[2]);
            if (r1 < KMAX && c1 < GNUM) atomicAdd(&sC[r1 * 24 + c1], c[3]);
        }
    }
    __syncthreads();
    for (int i = tid; i < KMAX * GNUM; i += BT)
        atomicAdd(&g_A[i], sC[(i / GNUM) * 24 + (i % GNUM)]);

    // ---- last block finalizes (ticket) ----
    __threadfence();
    if (tid == 0)
        *s_last = (atomicAdd(&g_count, 1) == GRID - 1) ? 1 : 0;
    __syncthreads();
    if (*s_last && tid < KMAX) {
        const volatile float* A = g_A;
        float best = A[tid * GNUM + 0];
        int bi = 0;
        #pragma unroll
        for (int g = 1; g < GNUM; g++) {
            float v = A[tid * GNUM + g];
            if (v > best) { best = v; bi = g; }  // FIRST max == first min of ce
        }
        out[tid] = (float)bi;                    // output compared as float32
    }
}

extern "C" void kernel_launch(void* const* d_in, const int* in_sizes, int n_in,
                              void* d_out, int out_size) {
    int maxSize = 0;
    for (int i = 0; i < n_in; i++)
        if (in_sizes[i] > maxSize) maxSize = in_sizes[i];
    int idxA = -1, idxB = -1;
    for (int i = 0; i < n_in; i++) {
        if (in_sizes[i] == maxSize) {
            if (idxA < 0) idxA = i;
            else if (idxB < 0) idxB = i;
        }
    }
    if (idxB < 0) idxB = idxA;

    const void* bufA = d_in[idxA];
    const void* bufB = d_in[idxB];
    const int n = maxSize / KMAX;
    float* out = (float*)d_out;

    static int attr_done = 0;
    if (!attr_done) {
        cudaFuncSetAttribute(ms_accum_kernel,
                             cudaFuncAttributeMaxDynamicSharedMemorySize,
                             SMEM_TOTAL);
        attr_done = 1;
    }

    ms_init_kernel<<<1, 512>>>();
    ms_accum_kernel<<<GRID, BT, SMEM_TOTAL>>>(bufA, bufB, n, out);
    (void)out_size;
}

// round 14
// speedup vs baseline: 1.0016x; 1.0016x over previous
#include <cuda_runtime.h>
#include <cstdint>

#define KMAX 21
#define GNUM 20
#define WT   32                      // pixels per warp-tile (4 MMA chunks)
#define NW   8                       // warps per block
#define BT   (NW * 32)               // 256
#define GRID 592                     // 4 blocks/SM
#define NSTAGE 2
#define EPSF 1e-6f

#define SEG_SL_F (WT * KMAX)         // 672 floats
#define SEG_SL_B (SEG_SL_F * 4)      // 2688 B = 168 x 16B chunks
#define SC_B     (KMAX * 24 * 4)
#define SMEM_TOTAL (NW * NSTAGE * SEG_SL_B + SC_B + 16)   // ~45 KB/block

__device__ float g_A[KMAX * GNUM];
__device__ int   g_count;

__global__ void ms_init_kernel() {
    int t = threadIdx.x;
    if (t < KMAX * GNUM) g_A[t] = 0.0f;
    if (t == 0) g_count = 0;
}

__device__ __forceinline__ void cpasync16(uint32_t dst, const void* src) {
    asm volatile("cp.async.cg.shared.global [%0], [%1], 16;" :: "r"(dst), "l"(src));
}
__device__ __forceinline__ void cp_commit() { asm volatile("cp.async.commit_group;"); }
__device__ __forceinline__ void cp_wait1()  { asm volatile("cp.async.wait_group 1;"); }

__device__ __forceinline__ float dval(float p) {
    // log2 = positive multiple of ln -> same argmax as reference.
    return __log2f(p + EPSF) - __log2f(1.0f - p + EPSF);
}

// C[16x8] += A[16x8 tf32] x B[8x8 tf32]; layouts validated in R11/R12.
#define MMA8(c, A, B) asm volatile( \
    "mma.sync.aligned.m16n8k8.row.col.f32.tf32.tf32.f32 " \
    "{%0,%1,%2,%3}, {%4,%5,%6,%7}, {%8,%9}, {%0,%1,%2,%3};" \
    : "+f"((c)[0]), "+f"((c)[1]), "+f"((c)[2]), "+f"((c)[3]) \
    : "r"((A)[0]), "r"((A)[1]), "r"((A)[2]), "r"((A)[3]), \
      "r"((B)[0]), "r"((B)[1]))

// A[k,g] = sum_p d[p,k]*gt[g,p] as split-K GEMM.
// seg: cp.async double-buffered smem (only smem consumer).
// gt:  per-lane 20-bit register mask (20 coalesced LDG + OR), distributed to
//      B-fragments via __shfl + bit-test (bits >=20 are zero -> no edge cases).
__global__ __launch_bounds__(BT, 4) void ms_accum_kernel(
    const void* bufA, const void* bufB, int n, float* __restrict__ out)
{
    extern __shared__ __align__(16) char smem[];
    float* sC     = (float*)(smem + NW * NSTAGE * SEG_SL_B);
    int*   s_last = (int*)(smem + NW * NSTAGE * SEG_SL_B + SC_B);

    const int tid  = threadIdx.x;
    const int lane = tid & 31;
    const int wid  = tid >> 5;
    const int tig  = lane & 3;
    const int gid  = lane >> 2;

    // ---- buffer-identity probe (gt words are {0,1}) ----
    const unsigned wA = ((const unsigned*)bufA)[lane];
    const bool a_is_gt = (__ballot_sync(0xffffffffu, wA > 1u) == 0u);
    const float* seg = (const float*)(a_is_gt ? bufB : bufA);  // (N,21) f32
    const int*   gtp = (const int*)  (a_is_gt ? bufA : bufB);  // (21,N) {0,1}

    for (int i = tid; i < KMAX * 24; i += BT) sC[i] = 0.0f;
    __syncthreads();

    // ---- balanced warp-tile range ----
    const int gw   = blockIdx.x * NW + wid;
    const int GW   = GRID * NW;
    const int totT = (n + WT - 1) / WT;
    const int w0 = (int)(((long long)gw * totT) / GW);
    const int w1 = (int)(((long long)(gw + 1) * totT) / GW);

    char* mySl = smem + wid * NSTAGE * SEG_SL_B;

    auto prefetch = [&](int t) {
        if (t < w1) {
            const int base = t * WT;
            const int cnt  = min(WT, n - base);
            char* sl = mySl + (t & 1) * SEG_SL_B;
            const uint32_t segd = (uint32_t)__cvta_generic_to_shared(sl);
            if (cnt == WT) {
                const float* sb = seg + (long long)base * KMAX;  // 16B-aligned
                #pragma unroll
                for (int r = 0; r < 6; r++) {              // 168 chunks
                    const int c = lane + r * 32;
                    if (c < SEG_SL_B / 16)
                        cpasync16(segd + c * 16, sb + c * 4);
                }
            } else {
                // ragged tail: pad seg with 0.5 (d=0), masks handle B side
                for (int i = lane; i < SEG_SL_F; i += 32) {
                    float v = (i < cnt * KMAX)
                        ? __ldg(seg + (long long)base * KMAX + i) : 0.5f;
                    *(float*)(sl + i * 4) = v;
                }
            }
        }
        cp_commit();          // unconditional: keeps group count consistent
    };

    float acc[6][4];
    #pragma unroll
    for (int i = 0; i < 6; i++)
        #pragma unroll
        for (int j = 0; j < 4; j++) acc[i][j] = 0.0f;

    prefetch(w0);
    prefetch(w0 + 1);

    for (int t = w0; t < w1; t++) {
        // ---- per-lane mask for pixel (t*WT + lane): 20 coalesced LDGs,
        //      issued BEFORE the cp wait so both latencies overlap ----
        unsigned myMask = 0;
        {
            const int px = t * WT + lane;
            if (px < n) {
                #pragma unroll
                for (int g = 0; g < GNUM; g++)
                    myMask |= (__ldg(gtp + (long long)g * n + px) != 0 ? 1u : 0u) << g;
            }
        }

        cp_wait1();
        __syncwarp();

        const float* ss = (const float*)(mySl + (t & 1) * SEG_SL_B);

        #pragma unroll
        for (int ch = 0; ch < WT / 8; ch++) {
            const int p0 = ch * 8 + tig, p1 = p0 + 4;

            // A frags: d computed inline, each (p,k) exactly once
            uint32_t a0[4], a1[4];
            a0[0] = __float_as_uint(dval(ss[p0 * KMAX + gid]));
            a0[1] = __float_as_uint(dval(ss[p0 * KMAX + gid + 8]));
            a0[2] = __float_as_uint(dval(ss[p1 * KMAX + gid]));
            a0[3] = __float_as_uint(dval(ss[p1 * KMAX + gid + 8]));
            const int r2 = 16 + gid;
            const int r2s = (r2 < KMAX) ? r2 : 0;
            float e0 = dval(ss[p0 * KMAX + r2s]);
            float e1 = dval(ss[p1 * KMAX + r2s]);
            if (r2 >= KMAX) { e0 = 0.0f; e1 = 0.0f; }
            a1[0] = __float_as_uint(e0);
            a1[1] = 0u;
            a1[2] = __float_as_uint(e1);
            a1[3] = 0u;

            // B frags via shfl'd register masks (bits >=20 are zero)
            const unsigned m0 = __shfl_sync(0xffffffffu, myMask, p0);
            const unsigned m1 = __shfl_sync(0xffffffffu, myMask, p1);
            uint32_t b[3][2];
            #pragma unroll
            for (int nt = 0; nt < 3; nt++) {
                const int nn = nt * 8 + gid;
                b[nt][0] = __float_as_uint(((m0 >> nn) & 1u) ? 1.0f : 0.0f);
                b[nt][1] = __float_as_uint(((m1 >> nn) & 1u) ? 1.0f : 0.0f);
            }

            #pragma unroll
            for (int nt = 0; nt < 3; nt++) {
                MMA8(acc[nt],     a0, b[nt]);   // planes 0..15
                MMA8(acc[3 + nt], a1, b[nt]);   // planes 16..20
            }
        }
        __syncwarp();
        prefetch(t + NSTAGE);
    }

    // ---- C frags -> smem block reduce ----
    #pragma unroll
    for (int mt = 0; mt < 2; mt++) {
        #pragma unroll
        for (int nt = 0; nt < 3; nt++) {
            const float* c = acc[mt * 3 + nt];
            const int r0 = mt * 16 + gid, r1 = r0 + 8;
            const int c0 = nt * 8 + 2 * tig, c1 = c0 + 1;
            if (r0 < KMAX && c0 < GNUM) atomicAdd(&sC[r0 * 24 + c0], c[0]);
            if (r0 < KMAX && c1 < GNUM) atomicAdd(&sC[r0 * 24 + c1], c[1]);
            if (r1 < KMAX && c0 < GNUM) atomicAdd(&sC[r1 * 24 + c0], c[2]);
            if (r1 < KMAX && c1 < GNUM) atomicAdd(&sC[r1 * 24 + c1], c[3]);
        }
    }
    __syncthreads();
    for (int i = tid; i < KMAX * GNUM; i += BT)
        atomicAdd(&g_A[i], sC[(i / GNUM) * 24 + (i % GNUM)]);

    // ---- last block finalizes (ticket) ----
    __threadfence();
    if (tid == 0)
        *s_last = (atomicAdd(&g_count, 1) == GRID - 1) ? 1 : 0;
    __syncthreads();
    if (*s_last && tid < KMAX) {
        const volatile float* A = g_A;
        float best = A[tid * GNUM + 0];
        int bi = 0;
        #pragma unroll
        for (int g = 1; g < GNUM; g++) {
            float v = A[tid * GNUM + g];
            if (v > best) { best = v; bi = g; }  // FIRST max == first min of ce
        }
        out[tid] = (float)bi;                    // output compared as float32
    }
}

extern "C" void kernel_launch(void* const* d_in, const int* in_sizes, int n_in,
                              void* d_out, int out_size) {
    int maxSize = 0;
    for (int i = 0; i < n_in; i++)
        if (in_sizes[i] > maxSize) maxSize = in_sizes[i];
    int idxA = -1, idxB = -1;
    for (int i = 0; i < n_in; i++) {
        if (in_sizes[i] == maxSize) {
            if (idxA < 0) idxA = i;
            else if (idxB < 0) idxB = i;
        }
    }
    if (idxB < 0) idxB = idxA;

    const void* bufA = d_in[idxA];
    const void* bufB = d_in[idxB];
    const int n = maxSize / KMAX;
    float* out = (float*)d_out;

    static int attr_done = 0;
    if (!attr_done) {
        cudaFuncSetAttribute(ms_accum_kernel,
                             cudaFuncAttributeMaxDynamicSharedMemorySize,
                             SMEM_TOTAL);
        attr_done = 1;
    }

    ms_init_kernel<<<1, 512>>>();
    ms_accum_kernel<<<GRID, BT, SMEM_TOTAL>>>(bufA, bufB, n, out);
    (void)out_size;
}

// round 15
// speedup vs baseline: 1.0846x; 1.0829x over previous
#include <cuda_runtime.h>
#include <cstdint>

#define KMAX 21
#define GNUM 20
#define WT   32                      // pixels per warp-tile (4 MMA chunks)
#define NW   6                       // warps per block
#define BT   (NW * 32)               // 192
#define GRID 296                     // 2 blocks/SM
#define NSTAGE 3                     // overlap = 2 compute-tiles > LDGSTS latency
#define EPSF 1e-6f

#define SEG_SL_F (WT * KMAX)         // 672 floats
#define SEG_SL_B (SEG_SL_F * 4)      // 2688 B (168 x 16B chunks)
#define GT_ROW_W 36                  // padded plane stride: 144B, 16B-aligned;
                                     // B-frag bank (4*gid+tig)%32 -> conflict-free
#define GT_SL_B  (GNUM * GT_ROW_W * 4)   // 2880 B
#define SLICE_B  (SEG_SL_B + GT_SL_B)    // 5568 B
#define SC_B     (KMAX * 24 * 4)
#define SMEM_TOTAL (NW * NSTAGE * SLICE_B + SC_B + 16)   // ~100 KB -> 2 blk/SM

__device__ float g_A[KMAX * GNUM];
__device__ int   g_count;

__global__ void ms_init_kernel() {
    int t = threadIdx.x;
    if (t < KMAX * GNUM) g_A[t] = 0.0f;
    if (t == 0) g_count = 0;
}

__device__ __forceinline__ void cpasync16(uint32_t dst, const void* src) {
    asm volatile("cp.async.cg.shared.global [%0], [%1], 16;" :: "r"(dst), "l"(src));
}
__device__ __forceinline__ void cp_commit() { asm volatile("cp.async.commit_group;"); }
__device__ __forceinline__ void cp_wait2()  { asm volatile("cp.async.wait_group 2;"); }

__device__ __forceinline__ float dval(float p) {
    // log2 = positive multiple of ln -> same argmax as reference.
    return __log2f(p + EPSF) - __log2f(1.0f - p + EPSF);
}

// C[16x8] += A[16x8 tf32] x B[8x8 tf32]; layouts validated in R11/R12.
#define MMA8(c, A, B) asm volatile( \
    "mma.sync.aligned.m16n8k8.row.col.f32.tf32.tf32.f32 " \
    "{%0,%1,%2,%3}, {%4,%5,%6,%7}, {%8,%9}, {%0,%1,%2,%3};" \
    : "+f"((c)[0]), "+f"((c)[1]), "+f"((c)[2]), "+f"((c)[3]) \
    : "r"((A)[0]), "r"((A)[1]), "r"((A)[2]), "r"((A)[3]), \
      "r"((B)[0]), "r"((B)[1]))

// A[k,g] = sum_p d[p,k]*gt[g,p] as split-K GEMM; each warp is an autonomous
// 3-stage cp.async pipeline over its own pixel range.
__global__ __launch_bounds__(BT, 2) void ms_accum_kernel(
    const void* bufA, const void* bufB, int n, float* __restrict__ out)
{
    extern __shared__ __align__(16) char smem[];
    float* sC     = (float*)(smem + NW * NSTAGE * SLICE_B);
    int*   s_last = (int*)(smem + NW * NSTAGE * SLICE_B + SC_B);

    const int tid  = threadIdx.x;
    const int lane = tid & 31;
    const int wid  = tid >> 5;
    const int tig  = lane & 3;
    const int gid  = lane >> 2;

    // ---- buffer-identity probe (gt words are {0,1}) ----
    const unsigned wA = ((const unsigned*)bufA)[lane];
    const bool a_is_gt = (__ballot_sync(0xffffffffu, wA > 1u) == 0u);
    const float* seg = (const float*)(a_is_gt ? bufB : bufA);  // (N,21) f32
    const int*   gtp = (const int*)  (a_is_gt ? bufA : bufB);  // (21,N) {0,1}

    for (int i = tid; i < KMAX * 24; i += BT) sC[i] = 0.0f;
    __syncthreads();

    // ---- balanced warp-tile range ----
    const int gw   = blockIdx.x * NW + wid;
    const int GW   = GRID * NW;
    const int totT = (n + WT - 1) / WT;
    const int w0 = (int)(((long long)gw * totT) / GW);
    const int w1 = (int)(((long long)(gw + 1) * totT) / GW);

    char* mySl = smem + wid * NSTAGE * SLICE_B;

    auto prefetch = [&](int t) {
        if (t < w1) {
            const int base = t * WT;
            const int cnt  = min(WT, n - base);
            char* sl = mySl + (t % NSTAGE) * SLICE_B;
            const uint32_t segd = (uint32_t)__cvta_generic_to_shared(sl);
            const uint32_t gtd  = segd + SEG_SL_B;
            if (cnt == WT) {
                const float* sb = seg + (long long)base * KMAX;  // 16B-aligned
                #pragma unroll
                for (int r = 0; r < 6; r++) {                 // 168 chunks
                    const int c = lane + r * 32;
                    if (c < SEG_SL_B / 16)
                        cpasync16(segd + c * 16, sb + c * 4);
                }
                #pragma unroll
                for (int r = 0; r < 5; r++) {                 // 160 chunks
                    const int c = lane + r * 32;
                    const int g = c >> 3, ch = c & 7;
                    cpasync16(gtd + (g * GT_ROW_W + ch * 4) * 4,
                              gtp + (long long)g * n + base + ch * 4);
                }
            } else {
                // ragged tail (unused when 32|n): scalar, zero-pad
                for (int i = lane; i < SEG_SL_F; i += 32) {
                    float v = (i < cnt * KMAX)
                        ? __ldg(seg + (long long)base * KMAX + i) : 0.5f;
                    *(float*)(sl + i * 4) = v;
                }
                for (int i = lane; i < GNUM * WT; i += 32) {
                    const int g = i >> 5, p = i & 31;
                    const int v = (p < cnt)
                        ? __ldg(gtp + (long long)g * n + base + p) : 0;
                    *(int*)(sl + SEG_SL_B + (g * GT_ROW_W + p) * 4) = v;
                }
            }
        }
        cp_commit();          // unconditional: keeps group count consistent
    };

    float acc[6][4];
    #pragma unroll
    for (int i = 0; i < 6; i++)
        #pragma unroll
        for (int j = 0; j < 4; j++) acc[i][j] = 0.0f;

    prefetch(w0);
    prefetch(w0 + 1);
    prefetch(w0 + 2);

    for (int t = w0; t < w1; t++) {
        cp_wait2();
        __syncwarp();

        const char*  sl  = mySl + (t % NSTAGE) * SLICE_B;
        const float* ss  = (const float*)sl;
        const int*   gts = (const int*)(sl + SEG_SL_B);

        #pragma unroll
        for (int ch = 0; ch < WT / 8; ch++) {
            const int p0 = ch * 8 + tig, p1 = p0 + 4;

            // A frags: d computed inline, each (p,k) exactly once
            uint32_t a0[4], a1[4];
            a0[0] = __float_as_uint(dval(ss[p0 * KMAX + gid]));
            a0[1] = __float_as_uint(dval(ss[p0 * KMAX + gid + 8]));
            a0[2] = __float_as_uint(dval(ss[p1 * KMAX + gid]));
            a0[3] = __float_as_uint(dval(ss[p1 * KMAX + gid + 8]));
            const int r2 = 16 + gid;
            const int r2s = (r2 < KMAX) ? r2 : 0;
            float e0 = dval(ss[p0 * KMAX + r2s]);
            float e1 = dval(ss[p1 * KMAX + r2s]);
            if (r2 >= KMAX) { e0 = 0.0f; e1 = 0.0f; }
            a1[0] = __float_as_uint(e0);
            a1[1] = 0u;
            a1[2] = __float_as_uint(e1);
            a1[3] = 0u;

            // B frags: gi as 0.0/1.0; stride 36 words -> conflict-free
            uint32_t b[3][2];
            #pragma unroll
            for (int nt = 0; nt < 3; nt++) {
                const int nn = nt * 8 + gid;
                float f0 = 0.0f, f1 = 0.0f;
                if (nn < GNUM) {
                    f0 = (float)gts[nn * GT_ROW_W + p0];
                    f1 = (float)gts[nn * GT_ROW_W + p1];
                }
                b[nt][0] = __float_as_uint(f0);
                b[nt][1] = __float_as_uint(f1);
            }

            #pragma unroll
            for (int nt = 0; nt < 3; nt++) {
                MMA8(acc[nt],     a0, b[nt]);   // planes 0..15
                MMA8(acc[3 + nt], a1, b[nt]);   // planes 16..20
            }
        }
        __syncwarp();
        prefetch(t + NSTAGE);
    }

    // ---- C frags -> smem block reduce ----
    #pragma unroll
    for (int mt = 0; mt < 2; mt++) {
        #pragma unroll
        for (int nt = 0; nt < 3; nt++) {
            const float* c = acc[mt * 3 + nt];
            const int r0 = mt * 16 + gid, r1 = r0 + 8;
            const int c0 = nt * 8 + 2 * tig, c1 = c0 + 1;
            if (r0 < KMAX && c0 < GNUM) atomicAdd(&sC[r0 * 24 + c0], c[0]);
            if (r0 < KMAX && c1 < GNUM) atomicAdd(&sC[r0 * 24 + c1], c[1]);
            if (r1 < KMAX && c0 < GNUM) atomicAdd(&sC[r1 * 24 + c0], c[2]);
            if (r1 < KMAX && c1 < GNUM) atomicAdd(&sC[r1 * 24 + c1], c[3]);
        }
    }
    __syncthreads();
    for (int i = tid; i < KMAX * GNUM; i += BT)
        atomicAdd(&g_A[i], sC[(i / GNUM) * 24 + (i % GNUM)]);

    // ---- last block finalizes (ticket) ----
    __threadfence();
    if (tid == 0)
        *s_last = (atomicAdd(&g_count, 1) == GRID - 1) ? 1 : 0;
    __syncthreads();
    if (*s_last && tid < KMAX) {
        const volatile float* A = g_A;
        float best = A[tid * GNUM + 0];
        int bi = 0;
        #pragma unroll
        for (int g = 1; g < GNUM; g++) {
            float v = A[tid * GNUM + g];
            if (v > best) { best = v; bi = g; }  // FIRST max == first min of ce
        }
        out[tid] = (float)bi;                    // output compared as float32
    }
}

extern "C" void kernel_launch(void* const* d_in, const int* in_sizes, int n_in,
                              void* d_out, int out_size) {
    int maxSize = 0;
    for (int i = 0; i < n_in; i++)
        if (in_sizes[i] > maxSize) maxSize = in_sizes[i];
    int idxA = -1, idxB = -1;
    for (int i = 0; i < n_in; i++) {
        if (in_sizes[i] == maxSize) {
            if (idxA < 0) idxA = i;
            else if (idxB < 0) idxB = i;
        }
    }
    if (idxB < 0) idxB = idxA;

    const void* bufA = d_in[idxA];
    const void* bufB = d_in[idxB];
    const int n = maxSize / KMAX;
    float* out = (float*)d_out;

    static int attr_done = 0;
    if (!attr_done) {
        cudaFuncSetAttribute(ms_accum_kernel,
                             cudaFuncAttributeMaxDynamicSharedMemorySize,
                             SMEM_TOTAL);
        attr_done = 1;
    }

    ms_init_kernel<<<1, 512>>>();
    ms_accum_kernel<<<GRID, BT, SMEM_TOTAL>>>(bufA, bufB, n, out);
    (void)out_size;
}